// round 2
// baseline (speedup 1.0000x reference)
#include <cuda_runtime.h>

// FrustumPooling (Lift-Splat-Shoot BEV pool), sm_103a
// Shapes: x (B,N,D,H,W,C) f32; intrinsics (B,N,3,3); pose (B,N,4,4)
// out (B, NZ*C, NY, NX) f32

namespace {
constexpr int Bc = 2, Nc = 4, Dc = 48, Hc = 28, Wc = 60, Cc = 64;
constexpr int NXc = 192, NYc = 192, NZc = 1;
constexpr int VOX = Bc * NZc * NYc * NXc;   // 73728
constexpr int SCR = VOX * Cc;               // 4,718,592 floats (18.9 MB)
constexpr int NCOL = Bc * Nc * Dc * Wc;     // 23040 warp-columns
}

__device__ float g_combine[Bc * Nc * 9];
__device__ float g_trans[Bc * Nc * 3];
__device__ float g_scratch[SCR];

// ---------------------------------------------------------------------------
// k_combine: per (b,n) compute combine = R @ inv(K) and trans. 8 threads.
// Adjugate inverse: for this (upper-triangular) K every entry is an exact
// ratio, matching jnp.linalg.inv's LU back-substitution bitwise.
// ---------------------------------------------------------------------------
__global__ void k_combine(const float* __restrict__ intr,
                          const float* __restrict__ pose) {
    int t = threadIdx.x;
    if (t >= Bc * Nc) return;
    const float* a = intr + t * 9;
    float det = a[0] * (a[4] * a[8] - a[5] * a[7])
              - a[1] * (a[3] * a[8] - a[5] * a[6])
              + a[2] * (a[3] * a[7] - a[4] * a[6]);
    float inv[9];
    inv[0] = (a[4] * a[8] - a[5] * a[7]) / det;
    inv[1] = (a[2] * a[7] - a[1] * a[8]) / det;
    inv[2] = (a[1] * a[5] - a[2] * a[4]) / det;
    inv[3] = (a[5] * a[6] - a[3] * a[8]) / det;
    inv[4] = (a[0] * a[8] - a[2] * a[6]) / det;
    inv[5] = (a[2] * a[3] - a[0] * a[5]) / det;
    inv[6] = (a[3] * a[7] - a[4] * a[6]) / det;
    inv[7] = (a[1] * a[6] - a[0] * a[7]) / det;
    inv[8] = (a[0] * a[4] - a[1] * a[3]) / det;
    const float* p = pose + t * 16;
    for (int i = 0; i < 3; i++) {
        for (int j = 0; j < 3; j++) {
            float s = __fadd_rn(
                __fadd_rn(__fmul_rn(p[i * 4 + 0], inv[0 * 3 + j]),
                          __fmul_rn(p[i * 4 + 1], inv[1 * 3 + j])),
                __fmul_rn(p[i * 4 + 2], inv[2 * 3 + j]));
            g_combine[t * 9 + i * 3 + j] = s;
        }
        g_trans[t * 3 + i] = p[i * 4 + 3];
    }
}

// ---------------------------------------------------------------------------
// k_zero: zero the scratch accumulator (float4 stores).
// ---------------------------------------------------------------------------
__global__ void k_zero() {
    int i = blockIdx.x * blockDim.x + threadIdx.x;   // grid sized exactly
    ((float4*)g_scratch)[i] = make_float4(0.f, 0.f, 0.f, 0.f);
}

// ---------------------------------------------------------------------------
// k_scatter: one warp per (b,n,d,w) column; iterate h, register-accumulate
// runs that hit the same voxel, flush with 2 coalesced atomicAdds per lane.
// Explicit __fmul_rn/__fadd_rn to forbid FMA contraction (gx sits exactly
// on integer boundaries for this geometry; contraction could flip trunc).
// ---------------------------------------------------------------------------
__global__ void __launch_bounds__(256) k_scatter(const float* __restrict__ x) {
    int gw = (blockIdx.x * blockDim.x + threadIdx.x) >> 5;
    int lane = threadIdx.x & 31;
    if (gw >= NCOL) return;
    int w = gw % Wc; int t = gw / Wc;
    int d = t % Dc;  t /= Dc;
    int n = t % Nc;  int b = t / Nc;
    int bn = b * Nc + n;

    const float* cm = g_combine + bn * 9;
    float c00 = cm[0], c01 = cm[1], c02 = cm[2];
    float c10 = cm[3], c11 = cm[4], c12 = cm[5];
    float c20 = cm[6], c21 = cm[7], c22 = cm[8];
    float t0 = g_trans[bn * 3 + 0];
    float t1 = g_trans[bn * 3 + 1];
    float t2 = g_trans[bn * 3 + 2];

    float dv = 2.0f + (float)d;                          // DMIN + d*DSTEP
    float u  = (float)w * (479.0f / 59.0f);              // linspace step (f32)
    float udv = __fmul_rn(u, dv);
    const float stepy = 223.0f / 27.0f;

    const float* xp = x + ((size_t)(bn * Dc + d) * Hc * Wc + w) * Cc;
    const size_t hstride = (size_t)Wc * Cc;

    float2 acc = make_float2(0.f, 0.f);
    int cur = -1;

    for (int h = 0; h < Hc; ++h) {
        float v   = (float)h * stepy;
        float vdv = __fmul_rn(v, dv);
        float g0 = __fadd_rn(__fadd_rn(__fadd_rn(__fmul_rn(c00, udv),
                         __fmul_rn(c01, vdv)), __fmul_rn(c02, dv)), t0);
        float g1 = __fadd_rn(__fadd_rn(__fadd_rn(__fmul_rn(c10, udv),
                         __fmul_rn(c11, vdv)), __fmul_rn(c12, dv)), t1);
        float g2 = __fadd_rn(__fadd_rn(__fadd_rn(__fmul_rn(c20, udv),
                         __fmul_rn(c21, vdv)), __fmul_rn(c22, dv)), t2);

        int gx = (int)__fadd_rn(__fmul_rn(g0, 4.0f), 96.0f);   // trunc = astype(int32)
        int gy = (int)__fadd_rn(__fmul_rn(g1, 4.0f), 96.0f);
        int gz = (int)(__fadd_rn(g2, 10.0f) / 20.0f);

        bool kept = (gx >= 0) & (gx < NXc) & (gy >= 0) & (gy < NYc) &
                    (gz >= 0) & (gz < NZc);
        if (kept) {  // warp-uniform
            int flat = ((b * NZc + gz) * NYc + gy) * NXc + gx;
            if (flat != cur) {
                if (cur >= 0) {
                    float* p = g_scratch + (size_t)cur * Cc + lane * 2;
                    atomicAdd(p,     acc.x);
                    atomicAdd(p + 1, acc.y);
                }
                cur = flat; acc.x = 0.f; acc.y = 0.f;
            }
            float2 val = *((const float2*)(xp + (size_t)h * hstride) + lane);
            acc.x += val.x;
            acc.y += val.y;
        }
    }
    if (cur >= 0) {
        float* p = g_scratch + (size_t)cur * Cc + lane * 2;
        atomicAdd(p,     acc.x);
        atomicAdd(p + 1, acc.y);
    }
}

// ---------------------------------------------------------------------------
// k_transpose: scratch (B,NZ,NY,NX,C) -> out (B, NZ*C, NY, NX)
// smem-tiled so both the scratch read and the out write are 128B-coalesced.
// ---------------------------------------------------------------------------
__global__ void k_transpose(float* __restrict__ out) {
    __shared__ float tile[Cc][33];
    int x0 = blockIdx.x * 32;
    int y  = blockIdx.y;
    int bz = blockIdx.z;                  // b*NZ + z
    int tx = threadIdx.x, ty = threadIdx.y;

    const float* src = g_scratch + (((size_t)bz * NYc + y) * NXc + x0) * Cc;
    for (int xi = ty; xi < 32; xi += 8) {
        tile[tx]      [xi] = src[(size_t)xi * Cc + tx];
        tile[tx + 32] [xi] = src[(size_t)xi * Cc + 32 + tx];
    }
    __syncthreads();

    float* dst = out + (size_t)bz * Cc * (NYc * NXc) + (size_t)y * NXc + x0;
    for (int c = ty; c < Cc; c += 8)
        dst[(size_t)c * (NYc * NXc) + tx] = tile[c][tx];
}

// ---------------------------------------------------------------------------
extern "C" void kernel_launch(void* const* d_in, const int* in_sizes, int n_in,
                              void* d_out, int out_size) {
    const float* x = nullptr;
    const float* intr = nullptr;
    const float* pose = nullptr;
    for (int i = 0; i < n_in; i++) {
        if (in_sizes[i] == Bc * Nc * 9)       intr = (const float*)d_in[i];
        else if (in_sizes[i] == Bc * Nc * 16) pose = (const float*)d_in[i];
        else                                  x    = (const float*)d_in[i];
    }
    k_combine<<<1, 32>>>(intr, pose);
    k_zero<<<(SCR / 4) / 256, 256>>>();
    k_scatter<<<(NCOL * 32) / 256, 256>>>(x);
    dim3 tgrid(NXc / 32, NYc, Bc * NZc);
    dim3 tblk(32, 8);
    k_transpose<<<tgrid, tblk>>>((float*)d_out);
}

// round 3
// speedup vs baseline: 2.0703x; 2.0703x over previous
#include <cuda_runtime.h>

// FrustumPooling (Lift-Splat-Shoot BEV pool), sm_103a — direct-scatter version.
// x (B,N,D,H,W,C) f32; intrinsics (B,N,3,3); pose (B,N,4,4)
// out (B, NZ*C, NY, NX) f32

namespace {
constexpr int Bc = 2, Nc = 4, Dc = 48, Hc = 28, Wc = 60, Cc = 64;
constexpr int NXc = 192, NYc = 192, NZc = 1;
constexpr int PLANE = NYc * NXc;
constexpr int NCOL = Bc * Nc * Dc * Wc;     // 23040 warp-columns
}

// ---------------------------------------------------------------------------
// k_scatter: one warp per (b,n,d,w) column.
//  - lane = h computes geometry (one shot, no 28-iter serial loop)
//  - fast path (all kept h -> same voxel): unrolled float4 accumulation with
//    half-warp split (2 h in flight), one atomic flush into the FINAL layout
//  - generic fallback handles non-uniform voxels per column
// combine = R @ inv(K) computed by 8 threads per block into smem (fused).
// ---------------------------------------------------------------------------
__global__ void __launch_bounds__(256) k_scatter(const float* __restrict__ x,
                                                 const float* __restrict__ intr,
                                                 const float* __restrict__ pose,
                                                 float* __restrict__ out) {
    __shared__ float s_cm[Bc * Nc][9];
    __shared__ float s_tr[Bc * Nc][3];

    if (threadIdx.x < Bc * Nc) {
        int t = threadIdx.x;
        const float* a = intr + t * 9;
        float det = a[0] * (a[4] * a[8] - a[5] * a[7])
                  - a[1] * (a[3] * a[8] - a[5] * a[6])
                  + a[2] * (a[3] * a[7] - a[4] * a[6]);
        float inv[9];
        inv[0] = (a[4] * a[8] - a[5] * a[7]) / det;
        inv[1] = (a[2] * a[7] - a[1] * a[8]) / det;
        inv[2] = (a[1] * a[5] - a[2] * a[4]) / det;
        inv[3] = (a[5] * a[6] - a[3] * a[8]) / det;
        inv[4] = (a[0] * a[8] - a[2] * a[6]) / det;
        inv[5] = (a[2] * a[3] - a[0] * a[5]) / det;
        inv[6] = (a[3] * a[7] - a[4] * a[6]) / det;
        inv[7] = (a[1] * a[6] - a[0] * a[7]) / det;
        inv[8] = (a[0] * a[4] - a[1] * a[3]) / det;
        const float* p = pose + t * 16;
        for (int i = 0; i < 3; i++) {
            for (int j = 0; j < 3; j++) {
                s_cm[t][i * 3 + j] = __fadd_rn(
                    __fadd_rn(__fmul_rn(p[i * 4 + 0], inv[0 * 3 + j]),
                              __fmul_rn(p[i * 4 + 1], inv[1 * 3 + j])),
                    __fmul_rn(p[i * 4 + 2], inv[2 * 3 + j]));
            }
            s_tr[t][i] = p[i * 4 + 3];
        }
    }
    __syncthreads();

    int gw = (blockIdx.x * blockDim.x + threadIdx.x) >> 5;   // grid is exact
    int lane = threadIdx.x & 31;
    int w = gw % Wc; int t = gw / Wc;
    int d = t % Dc;  t /= Dc;
    int n = t % Nc;  int b = t / Nc;
    int bn = b * Nc + n;

    float c00 = s_cm[bn][0], c01 = s_cm[bn][1], c02 = s_cm[bn][2];
    float c10 = s_cm[bn][3], c11 = s_cm[bn][4], c12 = s_cm[bn][5];
    float c20 = s_cm[bn][6], c21 = s_cm[bn][7], c22 = s_cm[bn][8];
    float t0 = s_tr[bn][0], t1 = s_tr[bn][1], t2 = s_tr[bn][2];

    float dv  = 2.0f + (float)d;                   // DMIN + d*DSTEP
    float u   = (float)w * (479.0f / 59.0f);       // linspace step (f32)
    float udv = __fmul_rn(u, dv);

    // lane = h geometry (exact FP sequence as the verified R1 kernel)
    int  h   = lane;
    float v   = (float)h * (223.0f / 27.0f);
    float vdv = __fmul_rn(v, dv);
    float g0 = __fadd_rn(__fadd_rn(__fadd_rn(__fmul_rn(c00, udv),
                     __fmul_rn(c01, vdv)), __fmul_rn(c02, dv)), t0);
    float g1 = __fadd_rn(__fadd_rn(__fadd_rn(__fmul_rn(c10, udv),
                     __fmul_rn(c11, vdv)), __fmul_rn(c12, dv)), t1);
    float g2 = __fadd_rn(__fadd_rn(__fadd_rn(__fmul_rn(c20, udv),
                     __fmul_rn(c21, vdv)), __fmul_rn(c22, dv)), t2);

    int gx = (int)__fadd_rn(__fmul_rn(g0, 4.0f), 96.0f);   // trunc = astype(int32)
    int gy = (int)__fadd_rn(__fmul_rn(g1, 4.0f), 96.0f);
    int gz = (int)(__fadd_rn(g2, 10.0f) / 20.0f);

    bool kept = (h < Hc) & (gx >= 0) & (gx < NXc) & (gy >= 0) & (gy < NYc) &
                (gz >= 0) & (gz < NZc);
    unsigned mask = __ballot_sync(0xffffffffu, kept);
    if (!mask) return;                                      // warp-uniform exit

    int pflat = (gz * NYc + gy) * NXc + gx;                 // voxel within (NZ,NY,NX)
    int leader = __ffs(mask) - 1;
    int f0 = __shfl_sync(0xffffffffu, pflat, leader);
    bool uni = __all_sync(0xffffffffu, (!kept) || (pflat == f0));

    const float* xp = x + ((size_t)(bn * Dc + d) * Hc * Wc + w) * Cc;
    const size_t hstride = (size_t)Wc * Cc;

    if (uni) {
        // ---- fast path: single voxel per column ----
        int half = lane >> 4;                 // half A: even h, half B: odd h
        int cl   = (lane & 15) << 2;          // channel base (float4)
        float4 acc = make_float4(0.f, 0.f, 0.f, 0.f);
        #pragma unroll
        for (int hh = 0; hh < Hc; hh += 2) {
            int myh = hh + half;
            if ((mask >> myh) & 1u) {
                float4 val = *(const float4*)(xp + (size_t)myh * hstride + cl);
                acc.x += val.x; acc.y += val.y; acc.z += val.z; acc.w += val.w;
            }
        }
        acc.x += __shfl_xor_sync(0xffffffffu, acc.x, 16);
        acc.y += __shfl_xor_sync(0xffffffffu, acc.y, 16);
        acc.z += __shfl_xor_sync(0xffffffffu, acc.z, 16);
        acc.w += __shfl_xor_sync(0xffffffffu, acc.w, 16);
        if (half == 0) {
            int z = f0 / PLANE, yx = f0 % PLANE;
            float* po = out + ((size_t)(b * NZc + z) * Cc + cl) * PLANE + yx;
            atomicAdd(po,              acc.x);
            atomicAdd(po +     PLANE,  acc.y);
            atomicAdd(po + 2 * PLANE,  acc.z);
            atomicAdd(po + 3 * PLANE,  acc.w);
        }
    } else {
        // ---- generic fallback: run-flush per voxel change (rare) ----
        float2 acc = make_float2(0.f, 0.f);
        int cur = -1;
        for (int hh = 0; hh < Hc; ++hh) {
            if (!((mask >> hh) & 1u)) continue;
            int f = __shfl_sync(0xffffffffu, pflat, hh);
            if (f != cur) {
                if (cur >= 0) {
                    int z = cur / PLANE, yx = cur % PLANE;
                    float* po = out + ((size_t)(b * NZc + z) * Cc + lane * 2) * PLANE + yx;
                    atomicAdd(po,         acc.x);
                    atomicAdd(po + PLANE, acc.y);
                }
                cur = f; acc.x = 0.f; acc.y = 0.f;
            }
            float2 val = *((const float2*)(xp + (size_t)hh * hstride) + lane);
            acc.x += val.x; acc.y += val.y;
        }
        if (cur >= 0) {
            int z = cur / PLANE, yx = cur % PLANE;
            float* po = out + ((size_t)(b * NZc + z) * Cc + lane * 2) * PLANE + yx;
            atomicAdd(po,         acc.x);
            atomicAdd(po + PLANE, acc.y);
        }
    }
}

// ---------------------------------------------------------------------------
extern "C" void kernel_launch(void* const* d_in, const int* in_sizes, int n_in,
                              void* d_out, int out_size) {
    const float* x = nullptr;
    const float* intr = nullptr;
    const float* pose = nullptr;
    for (int i = 0; i < n_in; i++) {
        if (in_sizes[i] == Bc * Nc * 9)       intr = (const float*)d_in[i];
        else if (in_sizes[i] == Bc * Nc * 16) pose = (const float*)d_in[i];
        else                                  x    = (const float*)d_in[i];
    }
    cudaMemsetAsync(d_out, 0, (size_t)out_size * sizeof(float), 0);
    k_scatter<<<(NCOL * 32) / 256, 256>>>(x, intr, pose, (float*)d_out);
}

// round 4
// speedup vs baseline: 2.6752x; 1.2922x over previous
#include <cuda_runtime.h>

// FrustumPooling (Lift-Splat-Shoot BEV pool), sm_103a — n-merged direct scatter.
// x (B,N,D,H,W,C) f32; intrinsics (B,N,3,3); pose (B,N,4,4)
// out (B, NZ*C, NY, NX) f32

namespace {
constexpr int Bc = 2, Nc = 4, Dc = 48, Hc = 28, Wc = 60, Cc = 64;
constexpr int NXc = 192, NYc = 192, NZc = 1;
constexpr int PLANE = NYc * NXc;
constexpr int NCOL = Bc * Dc * Wc;          // 5760 warp-columns (n folded in)
}

// ---------------------------------------------------------------------------
// k_scatter: one warp per (b,d,w); lane = h; n looped in registers.
// Fast path (all n, all kept h -> one voxel): 56-deep unrolled float4
// accumulation (half-warp h split), single full-warp atomic flush.
// Generic per-n run-flush fallback keeps input generality.
// ---------------------------------------------------------------------------
__global__ void __launch_bounds__(256) k_scatter(const float* __restrict__ x,
                                                 const float* __restrict__ intr,
                                                 const float* __restrict__ pose,
                                                 float* __restrict__ out) {
    __shared__ float s_cm[Bc * Nc][9];
    __shared__ float s_tr[Bc * Nc][3];

    if (threadIdx.x < Bc * Nc) {
        int t = threadIdx.x;
        const float* a = intr + t * 9;
        float det = a[0] * (a[4] * a[8] - a[5] * a[7])
                  - a[1] * (a[3] * a[8] - a[5] * a[6])
                  + a[2] * (a[3] * a[7] - a[4] * a[6]);
        float inv[9];
        inv[0] = (a[4] * a[8] - a[5] * a[7]) / det;
        inv[1] = (a[2] * a[7] - a[1] * a[8]) / det;
        inv[2] = (a[1] * a[5] - a[2] * a[4]) / det;
        inv[3] = (a[5] * a[6] - a[3] * a[8]) / det;
        inv[4] = (a[0] * a[8] - a[2] * a[6]) / det;
        inv[5] = (a[2] * a[3] - a[0] * a[5]) / det;
        inv[6] = (a[3] * a[7] - a[4] * a[6]) / det;
        inv[7] = (a[1] * a[6] - a[0] * a[7]) / det;
        inv[8] = (a[0] * a[4] - a[1] * a[3]) / det;
        const float* p = pose + t * 16;
        for (int i = 0; i < 3; i++) {
            for (int j = 0; j < 3; j++) {
                s_cm[t][i * 3 + j] = __fadd_rn(
                    __fadd_rn(__fmul_rn(p[i * 4 + 0], inv[0 * 3 + j]),
                              __fmul_rn(p[i * 4 + 1], inv[1 * 3 + j])),
                    __fmul_rn(p[i * 4 + 2], inv[2 * 3 + j]));
            }
            s_tr[t][i] = p[i * 4 + 3];
        }
    }
    __syncthreads();

    int gw = (blockIdx.x * blockDim.x + threadIdx.x) >> 5;   // grid is exact
    int lane = threadIdx.x & 31;
    int w = gw % Wc; int t = gw / Wc;
    int d = t % Dc;  int b = t / Dc;

    float dv  = 2.0f + (float)d;                   // DMIN + d*DSTEP
    float u   = (float)w * (479.0f / 59.0f);
    float udv = __fmul_rn(u, dv);
    float v   = (float)lane * (223.0f / 27.0f);    // lane = h
    float vdv = __fmul_rn(v, dv);

    unsigned masks[Nc];
    int flats[Nc];
    #pragma unroll
    for (int n = 0; n < Nc; n++) {
        int bn = b * Nc + n;
        float g0 = __fadd_rn(__fadd_rn(__fadd_rn(__fmul_rn(s_cm[bn][0], udv),
                     __fmul_rn(s_cm[bn][1], vdv)), __fmul_rn(s_cm[bn][2], dv)), s_tr[bn][0]);
        float g1 = __fadd_rn(__fadd_rn(__fadd_rn(__fmul_rn(s_cm[bn][3], udv),
                     __fmul_rn(s_cm[bn][4], vdv)), __fmul_rn(s_cm[bn][5], dv)), s_tr[bn][1]);
        float g2 = __fadd_rn(__fadd_rn(__fadd_rn(__fmul_rn(s_cm[bn][6], udv),
                     __fmul_rn(s_cm[bn][7], vdv)), __fmul_rn(s_cm[bn][8], dv)), s_tr[bn][2]);
        int gx = (int)__fadd_rn(__fmul_rn(g0, 4.0f), 96.0f);   // trunc = astype(int32)
        int gy = (int)__fadd_rn(__fmul_rn(g1, 4.0f), 96.0f);
        int gz = (int)(__fadd_rn(g2, 10.0f) / 20.0f);
        bool kept = (lane < Hc) & (gx >= 0) & (gx < NXc) & (gy >= 0) & (gy < NYc) &
                    (gz >= 0) & (gz < NZc);
        masks[n] = __ballot_sync(0xffffffffu, kept);
        flats[n] = (gz * NYc + gy) * NXc + gx;
    }
    unsigned any = masks[0] | masks[1] | masks[2] | masks[3];
    if (!any) return;                                          // warp-uniform exit

    // uniform-voxel check across lanes AND cameras
    bool uni = true;
    int fcom = -1;
    #pragma unroll
    for (int n = 0; n < Nc; n++) {
        if (masks[n]) {
            int f0 = __shfl_sync(0xffffffffu, flats[n], __ffs(masks[n]) - 1);
            bool keptn = (masks[n] >> lane) & 1u;
            bool un = __all_sync(0xffffffffu, (!keptn) || (flats[n] == f0));
            if (fcom < 0) fcom = f0;
            uni = uni && un && (f0 == fcom);
        }
    }

    const size_t nstride = (size_t)Dc * Hc * Wc * Cc;
    const size_t hstride = (size_t)Wc * Cc;
    const float* xp0 = x + ((size_t)(b * Nc * Dc + d) * Hc * Wc + w) * Cc;

    if (uni) {
        // ---- fast path: one voxel for the whole (b,d,w) column, all n ----
        int half = lane >> 4;                 // half A: even h, half B: odd h
        int cl   = (lane & 15) << 2;          // channel base (float4)
        float4 acc = make_float4(0.f, 0.f, 0.f, 0.f);
        #pragma unroll
        for (int hh = 0; hh < Hc; hh += 2) {
            int myh = hh + half;
            #pragma unroll
            for (int n = 0; n < Nc; n++) {
                if ((masks[n] >> myh) & 1u) {
                    float4 val = *(const float4*)(xp0 + n * nstride +
                                                  (size_t)myh * hstride + cl);
                    acc.x += val.x; acc.y += val.y; acc.z += val.z; acc.w += val.w;
                }
            }
        }
        acc.x += __shfl_xor_sync(0xffffffffu, acc.x, 16);
        acc.y += __shfl_xor_sync(0xffffffffu, acc.y, 16);
        acc.z += __shfl_xor_sync(0xffffffffu, acc.z, 16);
        acc.w += __shfl_xor_sync(0xffffffffu, acc.w, 16);
        // both halves now hold identical sums: lanes <16 flush ch cl,cl+1,
        // lanes >=16 flush ch cl+2,cl+3  -> 2 REDs/lane, full warp active
        int z = fcom / PLANE, yx = fcom % PLANE;
        int cbase = cl + half * 2;
        float vA = half ? acc.z : acc.x;
        float vB = half ? acc.w : acc.y;
        float* po = out + ((size_t)(b * NZc + z) * Cc + cbase) * PLANE + yx;
        atomicAdd(po,         vA);
        atomicAdd(po + PLANE, vB);
    } else {
        // ---- generic fallback: per-camera run-flush (rare) ----
        #pragma unroll
        for (int n = 0; n < Nc; n++) {
            if (!masks[n]) continue;
            const float* xp = xp0 + n * nstride;
            float2 acc = make_float2(0.f, 0.f);
            int cur = -1;
            for (int hh = 0; hh < Hc; ++hh) {
                if (!((masks[n] >> hh) & 1u)) continue;
                int f = __shfl_sync(0xffffffffu, flats[n], hh);
                if (f != cur) {
                    if (cur >= 0) {
                        int z = cur / PLANE, yx = cur % PLANE;
                        float* po = out + ((size_t)(b * NZc + z) * Cc + lane * 2) * PLANE + yx;
                        atomicAdd(po,         acc.x);
                        atomicAdd(po + PLANE, acc.y);
                    }
                    cur = f; acc.x = 0.f; acc.y = 0.f;
                }
                float2 val = *((const float2*)(xp + (size_t)hh * hstride) + lane);
                acc.x += val.x; acc.y += val.y;
            }
            if (cur >= 0) {
                int z = cur / PLANE, yx = cur % PLANE;
                float* po = out + ((size_t)(b * NZc + z) * Cc + lane * 2) * PLANE + yx;
                atomicAdd(po,         acc.x);
                atomicAdd(po + PLANE, acc.y);
            }
        }
    }
}

// ---------------------------------------------------------------------------
extern "C" void kernel_launch(void* const* d_in, const int* in_sizes, int n_in,
                              void* d_out, int out_size) {
    const float* x = nullptr;
    const float* intr = nullptr;
    const float* pose = nullptr;
    for (int i = 0; i < n_in; i++) {
        if (in_sizes[i] == Bc * Nc * 9)       intr = (const float*)d_in[i];
        else if (in_sizes[i] == Bc * Nc * 16) pose = (const float*)d_in[i];
        else                                  x    = (const float*)d_in[i];
    }
    cudaMemsetAsync(d_out, 0, (size_t)out_size * sizeof(float), 0);
    k_scatter<<<(NCOL * 32) / 256, 256>>>(x, intr, pose, (float*)d_out);
}

// round 5
// speedup vs baseline: 2.8750x; 1.0747x over previous
#include <cuda_runtime.h>

// FrustumPooling (Lift-Splat-Shoot BEV pool), sm_103a — n-pair split, branch-free loads.
// x (B,N,D,H,W,C) f32; intrinsics (B,N,3,3); pose (B,N,4,4)
// out (B, NZ*C, NY, NX) f32

namespace {
constexpr int Bc = 2, Nc = 4, Dc = 48, Hc = 28, Wc = 60, Cc = 64;
constexpr int NXc = 192, NYc = 192, NZc = 1;
constexpr int PLANE = NYc * NXc;
constexpr int NWARP = Bc * Dc * Wc * 2;     // 11520 warps (2 cam-pairs per column)
}

// ---------------------------------------------------------------------------
// k_scatter: warp = (b,d,w, campair); lane = h geometry; 2 cameras per warp.
// Fast path: 28 UNCONDITIONAL float4 loads (half-warp h split), mask applied
// as fmaf(m, val, acc) with m in {0,1} -> branch-free, deep LDG pipeline.
// One full-warp atomic flush into the final (B,C,NY,NX) layout.
// ---------------------------------------------------------------------------
__global__ void __launch_bounds__(256) k_scatter(const float* __restrict__ x,
                                                 const float* __restrict__ intr,
                                                 const float* __restrict__ pose,
                                                 float* __restrict__ out) {
    __shared__ float s_cm[Bc * Nc][9];
    __shared__ float s_tr[Bc * Nc][3];

    if (threadIdx.x < Bc * Nc) {
        int t = threadIdx.x;
        const float* a = intr + t * 9;
        float det = a[0] * (a[4] * a[8] - a[5] * a[7])
                  - a[1] * (a[3] * a[8] - a[5] * a[6])
                  + a[2] * (a[3] * a[7] - a[4] * a[6]);
        float inv[9];
        inv[0] = (a[4] * a[8] - a[5] * a[7]) / det;
        inv[1] = (a[2] * a[7] - a[1] * a[8]) / det;
        inv[2] = (a[1] * a[5] - a[2] * a[4]) / det;
        inv[3] = (a[5] * a[6] - a[3] * a[8]) / det;
        inv[4] = (a[0] * a[8] - a[2] * a[6]) / det;
        inv[5] = (a[2] * a[3] - a[0] * a[5]) / det;
        inv[6] = (a[3] * a[7] - a[4] * a[6]) / det;
        inv[7] = (a[1] * a[6] - a[0] * a[7]) / det;
        inv[8] = (a[0] * a[4] - a[1] * a[3]) / det;
        const float* p = pose + t * 16;
        for (int i = 0; i < 3; i++) {
            for (int j = 0; j < 3; j++) {
                s_cm[t][i * 3 + j] = __fadd_rn(
                    __fadd_rn(__fmul_rn(p[i * 4 + 0], inv[0 * 3 + j]),
                              __fmul_rn(p[i * 4 + 1], inv[1 * 3 + j])),
                    __fmul_rn(p[i * 4 + 2], inv[2 * 3 + j]));
            }
            s_tr[t][i] = p[i * 4 + 3];
        }
    }
    __syncthreads();

    int gw = (blockIdx.x * blockDim.x + threadIdx.x) >> 5;   // grid is exact
    int lane = threadIdx.x & 31;
    int npair = gw & 1;                  // cameras {0,1} or {2,3}
    int col = gw >> 1;
    int w = col % Wc; int t = col / Wc;
    int d = t % Dc;  int b = t / Dc;

    float dv  = 2.0f + (float)d;                   // DMIN + d*DSTEP
    float u   = (float)w * (479.0f / 59.0f);
    float udv = __fmul_rn(u, dv);
    float v   = (float)lane * (223.0f / 27.0f);    // lane = h
    float vdv = __fmul_rn(v, dv);

    unsigned masks[2];
    int flats[2];
    #pragma unroll
    for (int nn = 0; nn < 2; nn++) {
        int bn = b * Nc + npair * 2 + nn;
        float g0 = __fadd_rn(__fadd_rn(__fadd_rn(__fmul_rn(s_cm[bn][0], udv),
                     __fmul_rn(s_cm[bn][1], vdv)), __fmul_rn(s_cm[bn][2], dv)), s_tr[bn][0]);
        float g1 = __fadd_rn(__fadd_rn(__fadd_rn(__fmul_rn(s_cm[bn][3], udv),
                     __fmul_rn(s_cm[bn][4], vdv)), __fmul_rn(s_cm[bn][5], dv)), s_tr[bn][1]);
        float g2 = __fadd_rn(__fadd_rn(__fadd_rn(__fmul_rn(s_cm[bn][6], udv),
                     __fmul_rn(s_cm[bn][7], vdv)), __fmul_rn(s_cm[bn][8], dv)), s_tr[bn][2]);
        int gx = (int)__fadd_rn(__fmul_rn(g0, 4.0f), 96.0f);   // trunc = astype(int32)
        int gy = (int)__fadd_rn(__fmul_rn(g1, 4.0f), 96.0f);
        int gz = (int)(__fadd_rn(g2, 10.0f) / 20.0f);
        bool kept = (lane < Hc) & (gx >= 0) & (gx < NXc) & (gy >= 0) & (gy < NYc) &
                    (gz >= 0) & (gz < NZc);
        masks[nn] = __ballot_sync(0xffffffffu, kept);
        flats[nn] = (gz * NYc + gy) * NXc + gx;
    }
    unsigned any = masks[0] | masks[1];
    if (!any) return;                                          // warp-uniform exit

    // uniform-voxel check across lanes AND this warp's 2 cameras
    bool uni = true;
    int fcom = -1;
    #pragma unroll
    for (int nn = 0; nn < 2; nn++) {
        if (masks[nn]) {
            int f0 = __shfl_sync(0xffffffffu, flats[nn], __ffs(masks[nn]) - 1);
            bool keptn = (masks[nn] >> lane) & 1u;
            bool un = __all_sync(0xffffffffu, (!keptn) || (flats[nn] == f0));
            if (fcom < 0) fcom = f0;
            uni = uni && un && (f0 == fcom);
        }
    }

    const size_t nstride = (size_t)Dc * Hc * Wc * Cc;
    const size_t hstride = (size_t)Wc * Cc;
    const float* xp0 = x + ((size_t)((b * Nc + npair * 2) * Dc + d) * Hc * Wc + w) * Cc;

    if (uni) {
        // ---- fast path: branch-free, unconditional loads, fmaf-masked ----
        int half = lane >> 4;                 // half A: even h, half B: odd h
        int cl   = (lane & 15) << 2;          // channel base (float4)
        float4 acc = make_float4(0.f, 0.f, 0.f, 0.f);
        #pragma unroll
        for (int hh = 0; hh < Hc; hh += 2) {
            int myh = hh + half;
            #pragma unroll
            for (int nn = 0; nn < 2; nn++) {
                float4 val = *(const float4*)(xp0 + nn * nstride +
                                              (size_t)myh * hstride + cl);
                float m = (float)((masks[nn] >> myh) & 1u);
                acc.x = fmaf(m, val.x, acc.x);
                acc.y = fmaf(m, val.y, acc.y);
                acc.z = fmaf(m, val.z, acc.z);
                acc.w = fmaf(m, val.w, acc.w);
            }
        }
        acc.x += __shfl_xor_sync(0xffffffffu, acc.x, 16);
        acc.y += __shfl_xor_sync(0xffffffffu, acc.y, 16);
        acc.z += __shfl_xor_sync(0xffffffffu, acc.z, 16);
        acc.w += __shfl_xor_sync(0xffffffffu, acc.w, 16);
        // both halves hold identical sums: lanes<16 flush ch cl,cl+1,
        // lanes>=16 flush ch cl+2,cl+3 -> 2 REDs/lane, full warp active
        int z = fcom / PLANE, yx = fcom % PLANE;
        int cbase = cl + half * 2;
        float vA = half ? acc.z : acc.x;
        float vB = half ? acc.w : acc.y;
        float* po = out + ((size_t)(b * NZc + z) * Cc + cbase) * PLANE + yx;
        atomicAdd(po,         vA);
        atomicAdd(po + PLANE, vB);
    } else {
        // ---- generic fallback: per-camera run-flush (rare) ----
        #pragma unroll
        for (int nn = 0; nn < 2; nn++) {
            if (!masks[nn]) continue;
            const float* xp = xp0 + nn * nstride;
            float2 acc = make_float2(0.f, 0.f);
            int cur = -1;
            for (int hh = 0; hh < Hc; ++hh) {
                if (!((masks[nn] >> hh) & 1u)) continue;
                int f = __shfl_sync(0xffffffffu, flats[nn], hh);
                if (f != cur) {
                    if (cur >= 0) {
                        int z = cur / PLANE, yx = cur % PLANE;
                        float* po = out + ((size_t)(b * NZc + z) * Cc + lane * 2) * PLANE + yx;
                        atomicAdd(po,         acc.x);
                        atomicAdd(po + PLANE, acc.y);
                    }
                    cur = f; acc.x = 0.f; acc.y = 0.f;
                }
                float2 val = *((const float2*)(xp + (size_t)hh * hstride) + lane);
                acc.x += val.x; acc.y += val.y;
            }
            if (cur >= 0) {
                int z = cur / PLANE, yx = cur % PLANE;
                float* po = out + ((size_t)(b * NZc + z) * Cc + lane * 2) * PLANE + yx;
                atomicAdd(po,         acc.x);
                atomicAdd(po + PLANE, acc.y);
            }
        }
    }
}

// ---------------------------------------------------------------------------
extern "C" void kernel_launch(void* const* d_in, const int* in_sizes, int n_in,
                              void* d_out, int out_size) {
    const float* x = nullptr;
    const float* intr = nullptr;
    const float* pose = nullptr;
    for (int i = 0; i < n_in; i++) {
        if (in_sizes[i] == Bc * Nc * 9)       intr = (const float*)d_in[i];
        else if (in_sizes[i] == Bc * Nc * 16) pose = (const float*)d_in[i];
        else                                  x    = (const float*)d_in[i];
    }
    cudaMemsetAsync(d_out, 0, (size_t)out_size * sizeof(float), 0);
    k_scatter<<<(NWARP * 32) / 256, 256>>>(x, intr, pose, (float*)d_out);
}